// round 11
// baseline (speedup 1.0000x reference)
#include <cuda_runtime.h>
#include <cuda_bf16.h>
#include <cstdint>

#define MAX_N 50000
#define MAX_E 800000
#define HIDN 128

// ---------------- scratch (no allocations allowed) ----------------
__device__ float d_hp  [(size_t)MAX_N * HIDN];
__device__ float d_agg [(size_t)MAX_N * HIDN];
__device__ float d_t   [(size_t)MAX_N * HIDN];
__device__ float d_outl[(size_t)3 * MAX_N * HIDN];
__device__ float d_zcat[256 * 768];
__device__ float d_zh  [256 * 128];
__device__ float d_stats[6 * 256];   // 3 layers x 2 BN x (sum[128], sumsq[128])
__device__ float d_hsc[256];         // head scale/shift
__device__ __nv_bfloat16 d_whi[128 * 128];   // W split hi, [n][k] layout
__device__ __nv_bfloat16 d_wlo[128 * 128];   // W split lo, [n][k] layout
// CSR-by-dst (built once per launch; dst is layer-invariant)
__device__ int d_deg [MAX_N];
__device__ int d_ptr [MAX_N + 1];
__device__ int d_cur [MAX_N];
__device__ int d_esrc[MAX_E];
__device__ int d_eidx[MAX_E];

// ================= helpers =================
__device__ __forceinline__ uint32_t smem_to_u32(const void* smem_ptr) {
    uint32_t addr;
    asm("{ .reg .u64 tmp; cvta.to.shared.u64 tmp, %1; cvt.u32.u64 %0, tmp; }"
        : "=r"(addr) : "l"(smem_ptr));
    return addr;
}

__device__ __forceinline__ void ldsm4(uint32_t* r, uint32_t addr) {
    asm volatile("ldmatrix.sync.aligned.m8n8.x4.shared.b16 {%0,%1,%2,%3}, [%4];"
                 : "=r"(r[0]), "=r"(r[1]), "=r"(r[2]), "=r"(r[3]) : "r"(addr));
}

__device__ __forceinline__ void mma16816(float* d, const uint32_t* a, const uint32_t* b) {
    asm volatile(
        "mma.sync.aligned.m16n8k16.row.col.f32.bf16.bf16.f32 "
        "{%0,%1,%2,%3}, {%4,%5,%6,%7}, {%8,%9}, {%0,%1,%2,%3};"
        : "+f"(d[0]), "+f"(d[1]), "+f"(d[2]), "+f"(d[3])
        : "r"(a[0]), "r"(a[1]), "r"(a[2]), "r"(a[3]), "r"(b[0]), "r"(b[1]));
}

__device__ __forceinline__ uint32_t pack2(float a, float b) {
    __nv_bfloat162 t = __floats2bfloat162_rn(a, b);   // .x = a (low half)
    return *(uint32_t*)&t;
}

// ---------------- CSR build ----------------
__global__ __launch_bounds__(256) void hist_kernel(
    const int* __restrict__ dst, int E, int* __restrict__ deg)
{
    int i = blockIdx.x * 256 + threadIdx.x;
    if (i < E) atomicAdd(&deg[dst[i]], 1);
}

__global__ __launch_bounds__(1024) void scan_kernel(
    const int* __restrict__ deg, int n, int* __restrict__ ptr, int* __restrict__ cur)
{
    __shared__ int ssum[1024];
    const int tid = threadIdx.x;
    const int chunk = (n + 1023) >> 10;
    const int start = tid * chunk;
    int s = 0;
    for (int i = 0; i < chunk; i++) {
        int idx = start + i;
        if (idx < n) s += deg[idx];
    }
    ssum[tid] = s;
    __syncthreads();
    // Hillis-Steele inclusive scan
    for (int off = 1; off < 1024; off <<= 1) {
        int v = 0;
        if (tid >= off) v = ssum[tid - off];
        __syncthreads();
        ssum[tid] += v;
        __syncthreads();
    }
    int base = ssum[tid] - s;   // exclusive
    for (int i = 0; i < chunk; i++) {
        int idx = start + i;
        if (idx < n) {
            ptr[idx] = base;
            cur[idx] = base;
            base += deg[idx];
        }
    }
    if (tid == 1023) ptr[n] = ssum[1023];
}

__global__ __launch_bounds__(256) void scatter_kernel(
    const int* __restrict__ src, const int* __restrict__ dst, int E,
    int* __restrict__ cur, int* __restrict__ esrc, int* __restrict__ eidx)
{
    int i = blockIdx.x * 256 + threadIdx.x;
    if (i < E) {
        int p = atomicAdd(&cur[dst[i]], 1);
        esrc[p] = src[i];
        eidx[p] = i;
    }
}

// ---------------- W split: W[k][n] fp32 -> Whi/Wlo[n][k] bf16 ----------------
__global__ __launch_bounds__(256) void conv_w(
    const float* __restrict__ W,
    __nv_bfloat16* __restrict__ Whi, __nv_bfloat16* __restrict__ Wlo)
{
    for (int i = blockIdx.x * 256 + threadIdx.x; i < 128 * 128; i += gridDim.x * 256) {
        int k = i >> 7, n = i & 127;
        float v = W[i];
        __nv_bfloat16 h = __float2bfloat16(v);
        float lo = v - __bfloat162float(h);
        Whi[n * 128 + k] = h;
        Wlo[n * 128 + k] = __float2bfloat16(lo);
    }
}

// =================================================================
// HMMA GEMM: C[M x 128] = f(A[M x 128]) @ W[128 x 128] + bias
//   f = identity if gstats==nullptr, else relu(bn(A))
// fp32 emulated as bf16 split: Ahi*Bhi + Alo*Bhi + Ahi*Blo
// =================================================================
__global__ __launch_bounds__(256, 2) void mma_gemm(
    const float* __restrict__ A,
    const __nv_bfloat16* __restrict__ Whi, const __nv_bfloat16* __restrict__ Wlo,
    const float* __restrict__ bias,
    const float* __restrict__ gstats, const float* __restrict__ gamma,
    const float* __restrict__ beta, float invM,
    float* __restrict__ C, int M)
{
    __shared__ __align__(16) __nv_bfloat16 sAhi[128 * 40];
    __shared__ __align__(16) __nv_bfloat16 sAlo[128 * 40];
    __shared__ __align__(16) __nv_bfloat16 sBhi[128 * 40];
    __shared__ __align__(16) __nv_bfloat16 sBlo[128 * 40];
    __shared__ float sBias[128];
    __shared__ float sSc[128];
    __shared__ float sSh[128];

    const int tid = threadIdx.x;
    const int wid = tid >> 5, lane = tid & 31;
    const int wm = wid & 3, wn = wid >> 2;      // 4 (M) x 2 (N) warps
    const int m0 = blockIdx.x * 128;
    const bool dobn = (gstats != nullptr);

    if (tid < 128) {
        sBias[tid] = bias[tid];
        if (dobn) {
            float m = gstats[tid] * invM;
            float v = gstats[128 + tid] * invM - m * m;
            float sc = gamma[tid] * rsqrtf(v + 1e-5f);
            sSc[tid] = sc;
            sSh[tid] = beta[tid] - m * sc;
        }
    }
    __syncthreads();

    float acc[2][8][4];
    #pragma unroll
    for (int i = 0; i < 2; i++)
        #pragma unroll
        for (int j = 0; j < 8; j++)
            #pragma unroll
            for (int q = 0; q < 4; q++) acc[i][j][q] = 0.f;

    const uint32_t aHiB = smem_to_u32(sAhi), aLoB = smem_to_u32(sAlo);
    const uint32_t bHiB = smem_to_u32(sBhi), bLoB = smem_to_u32(sBlo);

    const uint32_t aoffL = (uint32_t)(((wm * 32 + (lane & 15)) * 40 + ((lane >> 4) << 3)) * 2);
    const uint32_t boffL = (uint32_t)(((wn * 64 + ((lane >> 4) << 3) + (lane & 7)) * 40
                                      + (((lane >> 3) & 1) << 3)) * 2);

    for (int kc = 0; kc < 128; kc += 32) {
        if (kc) __syncthreads();

        // ---- A chunk: 128 rows x 32 cols fp32 -> bf16 hi/lo ----
        #pragma unroll
        for (int i = 0; i < 4; i++) {
            int linear = tid + i * 256;
            int r = linear >> 3;
            int c4 = (linear & 7) * 4;
            int gr = m0 + r;
            float4 v = make_float4(0.f, 0.f, 0.f, 0.f);
            if (gr < M) {
                v = *(const float4*)(A + (size_t)gr * 128 + kc + c4);
                if (dobn) {
                    int kcc = kc + c4;
                    float4 sc = *(const float4*)&sSc[kcc];
                    float4 sh = *(const float4*)&sSh[kcc];
                    v.x = fmaxf(fmaf(v.x, sc.x, sh.x), 0.f);
                    v.y = fmaxf(fmaf(v.y, sc.y, sh.y), 0.f);
                    v.z = fmaxf(fmaf(v.z, sc.z, sh.z), 0.f);
                    v.w = fmaxf(fmaf(v.w, sc.w, sh.w), 0.f);
                }
            }
            __nv_bfloat16 hx = __float2bfloat16(v.x), hy = __float2bfloat16(v.y);
            __nv_bfloat16 hz = __float2bfloat16(v.z), hw = __float2bfloat16(v.w);
            float lx = v.x - __bfloat162float(hx), ly = v.y - __bfloat162float(hy);
            float lz = v.z - __bfloat162float(hz), lw = v.w - __bfloat162float(hw);
            int base = r * 40 + c4;
            __nv_bfloat162 h0; h0.x = hx; h0.y = hy;
            __nv_bfloat162 h1; h1.x = hz; h1.y = hw;
            *(uint32_t*)&sAhi[base]     = *(uint32_t*)&h0;
            *(uint32_t*)&sAhi[base + 2] = *(uint32_t*)&h1;
            *(uint32_t*)&sAlo[base]     = pack2(lx, ly);
            *(uint32_t*)&sAlo[base + 2] = pack2(lz, lw);
        }

        // ---- B chunk: copy pre-split [n][k] bf16 ----
        #pragma unroll
        for (int i = 0; i < 2; i++) {
            int linear = tid + i * 256;
            int r = linear >> 2;
            int c8 = (linear & 3) * 8;
            *(uint4*)&sBhi[r * 40 + c8] = *(const uint4*)(Whi + (size_t)r * 128 + kc + c8);
            *(uint4*)&sBlo[r * 40 + c8] = *(const uint4*)(Wlo + (size_t)r * 128 + kc + c8);
        }
        __syncthreads();

        #pragma unroll
        for (int ks = 0; ks < 2; ks++) {
            const uint32_t ko = (uint32_t)(ks * 16 * 2);
            uint32_t ahi[8], alo[8], bf[16];
            ldsm4(ahi,     aHiB + aoffL + ko);
            ldsm4(ahi + 4, aHiB + aoffL + ko + 16 * 40 * 2);
            ldsm4(alo,     aLoB + aoffL + ko);
            ldsm4(alo + 4, aLoB + aoffL + ko + 16 * 40 * 2);
            ldsm4(bf,      bHiB + boffL + ko);
            ldsm4(bf + 4,  bHiB + boffL + ko + 16 * 40 * 2);
            ldsm4(bf + 8,  bHiB + boffL + ko + 32 * 40 * 2);
            ldsm4(bf + 12, bHiB + boffL + ko + 48 * 40 * 2);
            #pragma unroll
            for (int mt = 0; mt < 2; mt++)
                #pragma unroll
                for (int nt = 0; nt < 8; nt++) {
                    mma16816(acc[mt][nt], ahi + mt * 4, bf + nt * 2);
                    mma16816(acc[mt][nt], alo + mt * 4, bf + nt * 2);
                }
            ldsm4(bf,      bLoB + boffL + ko);
            ldsm4(bf + 4,  bLoB + boffL + ko + 16 * 40 * 2);
            ldsm4(bf + 8,  bLoB + boffL + ko + 32 * 40 * 2);
            ldsm4(bf + 12, bLoB + boffL + ko + 48 * 40 * 2);
            #pragma unroll
            for (int mt = 0; mt < 2; mt++)
                #pragma unroll
                for (int nt = 0; nt < 8; nt++)
                    mma16816(acc[mt][nt], ahi + mt * 4, bf + nt * 2);
        }
    }

    #pragma unroll
    for (int mt = 0; mt < 2; mt++) {
        int r0 = m0 + wm * 32 + mt * 16 + (lane >> 2);
        #pragma unroll
        for (int nt = 0; nt < 8; nt++) {
            int c = wn * 64 + nt * 8 + (lane & 3) * 2;
            float b0 = sBias[c], b1 = sBias[c + 1];
            if (r0 < M) {
                float2 o = make_float2(acc[mt][nt][0] + b0, acc[mt][nt][1] + b1);
                *(float2*)(C + (size_t)r0 * 128 + c) = o;
            }
            if (r0 + 8 < M) {
                float2 o = make_float2(acc[mt][nt][2] + b0, acc[mt][nt][3] + b1);
                *(float2*)(C + (size_t)(r0 + 8) * 128 + c) = o;
            }
        }
    }
}

// =================================================================
// scalar GEMM (projection only, K=64): C = A@W + bias
// =================================================================
__global__ __launch_bounds__(256) void gemm_kernel(
    const float* __restrict__ A, const float* __restrict__ W,
    const float* __restrict__ bias,
    float* __restrict__ C, int M, int K)
{
    constexpr int BM = 128, BN = 128, BK = 16;
    __shared__ __align__(16) float As[BK][BM + 4];
    __shared__ __align__(16) float Bs[BK][BN];

    const int tid = threadIdx.x;
    const int m0 = blockIdx.x * BM;
    const int tx = tid & 15;
    const int ty = tid >> 4;

    float acc[8][8];
    #pragma unroll
    for (int i = 0; i < 8; i++)
        #pragma unroll
        for (int j = 0; j < 8; j++) acc[i][j] = 0.f;

    for (int kb = 0; kb < K; kb += BK) {
        #pragma unroll
        for (int i = 0; i < 2; i++) {
            int idx = tid + i * 256;
            int r = idx >> 2, c4 = idx & 3;
            int gr = m0 + r;
            float4 v = make_float4(0.f, 0.f, 0.f, 0.f);
            if (gr < M) v = *(const float4*)(A + (size_t)gr * K + kb + c4 * 4);
            As[c4 * 4 + 0][r] = v.x;
            As[c4 * 4 + 1][r] = v.y;
            As[c4 * 4 + 2][r] = v.z;
            As[c4 * 4 + 3][r] = v.w;
        }
        #pragma unroll
        for (int i = 0; i < 2; i++) {
            int idx = tid + i * 256;
            int r = idx >> 5, c4 = idx & 31;
            *(float4*)&Bs[r][c4 * 4] =
                *(const float4*)(W + (size_t)(kb + r) * BN + c4 * 4);
        }
        __syncthreads();

        #pragma unroll
        for (int kk = 0; kk < BK; kk++) {
            float4 a0 = *(const float4*)&As[kk][ty * 8];
            float4 a1 = *(const float4*)&As[kk][ty * 8 + 4];
            float4 b0 = *(const float4*)&Bs[kk][tx * 8];
            float4 b1 = *(const float4*)&Bs[kk][tx * 8 + 4];
            float av[8] = {a0.x, a0.y, a0.z, a0.w, a1.x, a1.y, a1.z, a1.w};
            float bv[8] = {b0.x, b0.y, b0.z, b0.w, b1.x, b1.y, b1.z, b1.w};
            #pragma unroll
            for (int i = 0; i < 8; i++)
                #pragma unroll
                for (int j = 0; j < 8; j++)
                    acc[i][j] = fmaf(av[i], bv[j], acc[i][j]);
        }
        __syncthreads();
    }

    float4 bv0 = *(const float4*)(bias + tx * 8);
    float4 bv1 = *(const float4*)(bias + tx * 8 + 4);
    float bb[8] = {bv0.x, bv0.y, bv0.z, bv0.w, bv1.x, bv1.y, bv1.z, bv1.w};

    #pragma unroll
    for (int i = 0; i < 8; i++) {
        int gr = m0 + ty * 8 + i;
        if (gr < M) {
            float4 o0 = make_float4(acc[i][0] + bb[0], acc[i][1] + bb[1],
                                    acc[i][2] + bb[2], acc[i][3] + bb[3]);
            float4 o1 = make_float4(acc[i][4] + bb[4], acc[i][5] + bb[5],
                                    acc[i][6] + bb[6], acc[i][7] + bb[7]);
            *(float4*)(C + (size_t)gr * BN + tx * 8)     = o0;
            *(float4*)(C + (size_t)gr * BN + tx * 8 + 4) = o1;
        }
    }
}

// ---------------- fast column stats: out[0..127]=sum, out[128..255]=sumsq ----------------
__global__ __launch_bounds__(256) void stats_fast(
    const float* __restrict__ T, int M, float* __restrict__ out)
{
    __shared__ float sS[8 * 128];
    __shared__ float sQ[8 * 128];
    const int tid = threadIdx.x, w = tid >> 5, l = tid & 31;
    const int c4 = l * 4;
    float4 s = make_float4(0.f, 0.f, 0.f, 0.f);
    float4 q = make_float4(0.f, 0.f, 0.f, 0.f);
    for (int r = blockIdx.x * 8 + w; r < M; r += gridDim.x * 8) {
        float4 v = *(const float4*)(T + (size_t)r * 128 + c4);
        s.x += v.x; q.x = fmaf(v.x, v.x, q.x);
        s.y += v.y; q.y = fmaf(v.y, v.y, q.y);
        s.z += v.z; q.z = fmaf(v.z, v.z, q.z);
        s.w += v.w; q.w = fmaf(v.w, v.w, q.w);
    }
    *(float4*)&sS[w * 128 + c4] = s;
    *(float4*)&sQ[w * 128 + c4] = q;
    __syncthreads();
    if (tid < 128) {
        float a = 0.f, b = 0.f;
        #pragma unroll
        for (int ww = 0; ww < 8; ww++) {
            a += sS[ww * 128 + tid];
            b += sQ[ww * 128 + tid];
        }
        atomicAdd(&out[tid], a);
        atomicAdd(&out[128 + tid], b);
    }
}

// =================================================================
// node-centric aggregation (atomic-free):
//   agg[n] = h[n] + sum_{e: dst[e]==n} relu(h[src[e]] + ea[e] @ We + be)
// one warp per node, CSR (ptr/esrc/eidx) built once per launch.
// =================================================================
__global__ __launch_bounds__(256) void node_agg(
    const float* __restrict__ h, const float* __restrict__ ea,
    const int* __restrict__ ptr, const int* __restrict__ esrc,
    const int* __restrict__ eidx,
    const float* __restrict__ We, const float* __restrict__ be,
    float* __restrict__ agg, int Nn)
{
    __shared__ __align__(16) float Ws[16][128];
    __shared__ __align__(16) float bs[128];
    const int tid = threadIdx.x;
    for (int i = tid; i < 16 * 128; i += 256) Ws[i >> 7][i & 127] = We[i];
    if (tid < 128) bs[tid] = be[tid];
    __syncthreads();

    const int warp = tid >> 5, lid = tid & 31;
    const int j0 = lid * 4;

    for (int n = blockIdx.x * 8 + warp; n < Nn; n += gridDim.x * 8) {
        const int lo = ptr[n], hi = ptr[n + 1];
        float4 acc = *(const float4*)(h + (size_t)n * 128 + j0);
        for (int e = lo; e < hi; e++) {
            int eid = __ldg(&eidx[e]);
            int s   = __ldg(&esrc[e]);
            float v = (lid < 16) ? __ldg(&ea[(size_t)eid * 16 + lid]) : 0.f;
            float4 hv = *(const float4*)(h + (size_t)s * 128 + j0);
            float4 m0 = *(const float4*)&bs[j0];
            float4 m1 = make_float4(0.f, 0.f, 0.f, 0.f);
            #pragma unroll
            for (int k = 0; k < 16; k += 2) {
                float a0 = __shfl_sync(0xffffffffu, v, k);
                float a1 = __shfl_sync(0xffffffffu, v, k + 1);
                float4 w0 = *(const float4*)&Ws[k][j0];
                float4 w1 = *(const float4*)&Ws[k + 1][j0];
                m0.x = fmaf(a0, w0.x, m0.x); m1.x = fmaf(a1, w1.x, m1.x);
                m0.y = fmaf(a0, w0.y, m0.y); m1.y = fmaf(a1, w1.y, m1.y);
                m0.z = fmaf(a0, w0.z, m0.z); m1.z = fmaf(a1, w1.z, m1.z);
                m0.w = fmaf(a0, w0.w, m0.w); m1.w = fmaf(a1, w1.w, m1.w);
            }
            acc.x += fmaxf(m0.x + m1.x + hv.x, 0.f);
            acc.y += fmaxf(m0.y + m1.y + hv.y, 0.f);
            acc.z += fmaxf(m0.z + m1.z + hv.z, 0.f);
            acc.w += fmaxf(m0.w + m1.w + hv.w, 0.f);
        }
        *(float4*)(agg + (size_t)n * 128 + j0) = acc;
    }
}

// ---------------- bn+relu apply ----------------
__global__ __launch_bounds__(256) void bn_apply_kernel(
    const float* __restrict__ T, const float* __restrict__ gstats,
    const float* __restrict__ gamma, const float* __restrict__ beta, float invM,
    float* __restrict__ outl, int total4)
{
    __shared__ float sSc[128];
    __shared__ float sSh[128];
    if (threadIdx.x < 128) {
        int c = threadIdx.x;
        float m = gstats[c] * invM;
        float v = gstats[128 + c] * invM - m * m;
        float sc = gamma[c] * rsqrtf(v + 1e-5f);
        sSc[c] = sc;
        sSh[c] = beta[c] - m * sc;
    }
    __syncthreads();
    int i = blockIdx.x * blockDim.x + threadIdx.x;
    if (i < total4) {
        int c4 = (i & 31) * 4;
        float4 v = *(const float4*)(T + (size_t)i * 4);
        float4 sc = *(const float4*)&sSc[c4];
        float4 sh = *(const float4*)&sSh[c4];
        float4 r;
        r.x = fmaxf(fmaf(v.x, sc.x, sh.x), 0.f);
        r.y = fmaxf(fmaf(v.y, sc.y, sh.y), 0.f);
        r.z = fmaxf(fmaf(v.z, sc.z, sh.z), 0.f);
        r.w = fmaxf(fmaf(v.w, sc.w, sh.w), 0.f);
        *(float4*)(outl + (size_t)i * 4) = r;
    }
}

// ---------------- pooling ----------------
__device__ __forceinline__ int lower_bound_i(const int* a, int n, int key) {
    int lo = 0, hi = n;
    while (lo < hi) { int mid = (lo + hi) >> 1; if (a[mid] < key) lo = mid + 1; else hi = mid; }
    return lo;
}

__global__ __launch_bounds__(384) void pool_kernel(
    const float* __restrict__ o0, const float* __restrict__ o1, const float* __restrict__ o2,
    const int* __restrict__ batch, int Nn, float* __restrict__ zcat)
{
    const int g = blockIdx.x;
    const int lo = lower_bound_i(batch, Nn, g);
    const int hi = lower_bound_i(batch, Nn, g + 1);
    const int c = threadIdx.x;
    const float* src = (c < 128) ? o0 : ((c < 256) ? o1 : o2);
    const int cc = c & 127;
    float s = 0.f, mx = 0.f;
    for (int n = lo; n < hi; n++) {
        float v = src[(size_t)n * 128 + cc];
        s += v; mx = fmaxf(mx, v);
    }
    int cnt = hi - lo;
    float mean = s / (float)(cnt > 0 ? cnt : 1);
    zcat[(size_t)g * 768 + c]       = mean;
    zcat[(size_t)g * 768 + 384 + c] = mx;
}

// ---------------- head ----------------
__global__ __launch_bounds__(128) void head1_kernel(
    const float* __restrict__ zcat, const float* __restrict__ W1,
    const float* __restrict__ b1, float* __restrict__ zh)
{
    __shared__ __align__(16) float zs[768];
    const int g = blockIdx.x;
    for (int k = threadIdx.x; k < 768; k += 128) zs[k] = zcat[(size_t)g * 768 + k];
    __syncthreads();
    const int j = threadIdx.x;
    float acc = b1[j];
    #pragma unroll 8
    for (int k = 0; k < 768; k++) acc = fmaf(zs[k], W1[(size_t)k * 128 + j], acc);
    zh[(size_t)g * 128 + j] = acc;
}

__global__ __launch_bounds__(128) void head_stats_kernel(
    const float* __restrict__ zh, const float* __restrict__ g, const float* __restrict__ b,
    int G, float* __restrict__ sc_sh)
{
    int c = threadIdx.x;
    float s = 0.f, s2 = 0.f;
    for (int r = 0; r < G; r++) { float v = zh[(size_t)r * 128 + c]; s += v; s2 = fmaf(v, v, s2); }
    float invG = 1.f / (float)G;
    float m = s * invG;
    float var = s2 * invG - m * m;
    float sc = g[c] * rsqrtf(var + 1e-5f);
    sc_sh[c] = sc;
    sc_sh[128 + c] = b[c] - m * sc;
}

__global__ __launch_bounds__(128) void head2_kernel(
    const float* __restrict__ zh, const float* __restrict__ sc_sh,
    const float* __restrict__ W2, const float* __restrict__ b2, float* __restrict__ out)
{
    __shared__ float red[128];
    const int g = blockIdx.x, j = threadIdx.x;
    float v = fmaxf(fmaf(zh[(size_t)g * 128 + j], sc_sh[j], sc_sh[128 + j]), 0.f) * W2[j];
    red[j] = v;
    __syncthreads();
    #pragma unroll
    for (int s = 64; s > 0; s >>= 1) {
        if (j < s) red[j] += red[j + s];
        __syncthreads();
    }
    if (j == 0) out[g] = red[0] + b2[0];
}

// ---------------- launcher ----------------
extern "C" void kernel_launch(void* const* d_in, const int* in_sizes, int n_in,
                              void* d_out, int out_size)
{
    const float* x         = (const float*)d_in[0];
    const float* edge_attr = (const float*)d_in[1];
    const int*   src       = (const int*)  d_in[2];
    const int*   dst       = (const int*)  d_in[3];
    const int*   batch     = (const int*)  d_in[4];
    const float* Wp        = (const float*)d_in[5];
    const float* bp        = (const float*)d_in[6];
    const float* conv_We   = (const float*)d_in[7];
    const float* conv_be   = (const float*)d_in[8];
    const float* conv_W1   = (const float*)d_in[9];
    const float* conv_b1   = (const float*)d_in[10];
    const float* conv_g1   = (const float*)d_in[11];
    const float* conv_bt1  = (const float*)d_in[12];
    const float* conv_W2   = (const float*)d_in[13];
    const float* conv_b2   = (const float*)d_in[14];
    const float* bn_g      = (const float*)d_in[15];
    const float* bn_b      = (const float*)d_in[16];
    const float* head_W1   = (const float*)d_in[17];
    const float* head_b1   = (const float*)d_in[18];
    const float* head_g    = (const float*)d_in[19];
    const float* head_bt   = (const float*)d_in[20];
    const float* head_W2   = (const float*)d_in[21];
    const float* head_b2   = (const float*)d_in[22];

    const int Nn = in_sizes[0] / 64;     // 50000
    const int E  = in_sizes[2];          // 800000
    const int G  = out_size;             // 256

    float *hp, *agg, *t, *outl, *zcat, *zh, *stats, *hsc;
    __nv_bfloat16 *whi, *wlo;
    int *deg, *ptr, *cur, *esrc, *eidx;
    cudaGetSymbolAddress((void**)&hp,    d_hp);
    cudaGetSymbolAddress((void**)&agg,   d_agg);
    cudaGetSymbolAddress((void**)&t,     d_t);
    cudaGetSymbolAddress((void**)&outl,  d_outl);
    cudaGetSymbolAddress((void**)&zcat,  d_zcat);
    cudaGetSymbolAddress((void**)&zh,    d_zh);
    cudaGetSymbolAddress((void**)&stats, d_stats);
    cudaGetSymbolAddress((void**)&hsc,   d_hsc);
    cudaGetSymbolAddress((void**)&whi,   d_whi);
    cudaGetSymbolAddress((void**)&wlo,   d_wlo);
    cudaGetSymbolAddress((void**)&deg,   d_deg);
    cudaGetSymbolAddress((void**)&ptr,   d_ptr);
    cudaGetSymbolAddress((void**)&cur,   d_cur);
    cudaGetSymbolAddress((void**)&esrc,  d_esrc);
    cudaGetSymbolAddress((void**)&eidx,  d_eidx);

    const int gB = (Nn + 127) / 128;
    const int gE = (E + 255) / 256;
    const float invM = 1.f / (float)Nn;
    const int total4 = Nn * 32;          // N*128/4

    // zero BN stat accumulators + degree histogram (re-done every launch -> replay-safe)
    cudaMemsetAsync(stats, 0, 6 * 256 * sizeof(float), 0);
    cudaMemsetAsync(deg, 0, (size_t)Nn * sizeof(int), 0);

    // CSR by dst (dst is layer-invariant; build once, use 3x)
    hist_kernel<<<gE, 256>>>(dst, E, deg);
    scan_kernel<<<1, 1024>>>(deg, Nn, ptr, cur);
    scatter_kernel<<<gE, 256>>>(src, dst, E, cur, esrc, eidx);

    // projection: h = x @ Wp + bp
    gemm_kernel<<<gB, 256>>>(x, Wp, bp, hp, Nn, 64);

    const float* h = hp;
    for (int l = 0; l < 3; l++) {
        const float* We_l = conv_We + (size_t)l * 16 * 128;
        const float* be_l = conv_be + (size_t)l * 128;
        const float* W1_l = conv_W1 + (size_t)l * 128 * 128;
        const float* b1_l = conv_b1 + (size_t)l * 128;
        const float* g1_l = conv_g1 + (size_t)l * 128;
        const float* t1_l = conv_bt1 + (size_t)l * 128;
        const float* W2_l = conv_W2 + (size_t)l * 128 * 128;
        const float* b2_l = conv_b2 + (size_t)l * 128;
        const float* bg_l = bn_g + (size_t)l * 128;
        const float* bb_l = bn_b + (size_t)l * 128;
        float* outl_l = outl + (size_t)l * Nn * 128;
        float* S0 = stats + (size_t)(2 * l) * 256;
        float* S1 = stats + (size_t)(2 * l + 1) * 256;

        // agg[n] = h[n] + sum incoming relu(h[src] + ea@We + be)   (atomic-free)
        node_agg<<<2048, 256>>>(h, edge_attr, ptr, esrc, eidx, We_l, be_l, agg, Nn);

        // t1 = agg @ W1 + b1 (HMMA bf16-split)
        conv_w<<<64, 256>>>(W1_l, whi, wlo);
        mma_gemm<<<gB, 256>>>(agg, whi, wlo, b1_l,
                              nullptr, nullptr, nullptr, 0.f, t, Nn);
        stats_fast<<<512, 256>>>(t, Nn, S0);

        // t2 = relu(bn_{S0}(t1)) @ W2 + b2 (in place, HMMA)
        conv_w<<<64, 256>>>(W2_l, whi, wlo);
        mma_gemm<<<gB, 256>>>(t, whi, wlo, b2_l,
                              S0, g1_l, t1_l, invM, t, Nn);
        stats_fast<<<512, 256>>>(t, Nn, S1);

        // out_l = relu(bn_{S1}(t2))
        bn_apply_kernel<<<(total4 + 255) / 256, 256>>>(
            t, S1, bg_l, bb_l, invM, outl_l, total4);

        h = outl_l;
    }

    pool_kernel<<<G, 384>>>(outl, outl + (size_t)Nn * 128, outl + (size_t)2 * Nn * 128,
                            batch, Nn, zcat);
    head1_kernel<<<G, 128>>>(zcat, head_W1, head_b1, zh);
    head_stats_kernel<<<1, 128>>>(zh, head_g, head_bt, G, hsc);
    head2_kernel<<<G, 128>>>(zh, hsc, head_W2, head_b2, (float*)d_out);
}

// round 12
// speedup vs baseline: 1.3446x; 1.3446x over previous
#include <cuda_runtime.h>
#include <cuda_bf16.h>
#include <cstdint>

#define MAX_N 50000
#define MAX_E 800000
#define HIDN 128

// ---------------- scratch (no allocations allowed) ----------------
__device__ float d_hp  [(size_t)MAX_N * HIDN];
__device__ float d_agg [(size_t)MAX_N * HIDN];
__device__ float d_t   [(size_t)MAX_N * HIDN];
__device__ float d_outl[(size_t)3 * MAX_N * HIDN];
__device__ float d_zcat[256 * 768];
__device__ float d_zh  [256 * 128];
__device__ float d_stats[6 * 256];   // 3 layers x 2 BN x (sum[128], sumsq[128])
__device__ float d_hsc[256];         // head scale/shift
__device__ __nv_bfloat16 d_whi[128 * 128];   // W split hi, [n][k] layout
__device__ __nv_bfloat16 d_wlo[128 * 128];   // W split lo, [n][k] layout
// CSR-by-dst (built once per launch; dst/edge_attr are layer-invariant)
__device__ int   d_deg [MAX_N];
__device__ int   d_ptr [MAX_N + 1];
__device__ int   d_cur [MAX_N];
__device__ int   d_esrc[MAX_E];
__device__ int   d_eidx[MAX_E];
__device__ float d_eas [(size_t)MAX_E * 16];  // edge_attr gathered into dst-sorted order

// ================= helpers =================
__device__ __forceinline__ uint32_t smem_to_u32(const void* smem_ptr) {
    uint32_t addr;
    asm("{ .reg .u64 tmp; cvta.to.shared.u64 tmp, %1; cvt.u32.u64 %0, tmp; }"
        : "=r"(addr) : "l"(smem_ptr));
    return addr;
}

__device__ __forceinline__ void ldsm4(uint32_t* r, uint32_t addr) {
    asm volatile("ldmatrix.sync.aligned.m8n8.x4.shared.b16 {%0,%1,%2,%3}, [%4];"
                 : "=r"(r[0]), "=r"(r[1]), "=r"(r[2]), "=r"(r[3]) : "r"(addr));
}

__device__ __forceinline__ void mma16816(float* d, const uint32_t* a, const uint32_t* b) {
    asm volatile(
        "mma.sync.aligned.m16n8k16.row.col.f32.bf16.bf16.f32 "
        "{%0,%1,%2,%3}, {%4,%5,%6,%7}, {%8,%9}, {%0,%1,%2,%3};"
        : "+f"(d[0]), "+f"(d[1]), "+f"(d[2]), "+f"(d[3])
        : "r"(a[0]), "r"(a[1]), "r"(a[2]), "r"(a[3]), "r"(b[0]), "r"(b[1]));
}

__device__ __forceinline__ uint32_t pack2(float a, float b) {
    __nv_bfloat162 t = __floats2bfloat162_rn(a, b);   // .x = a (low half)
    return *(uint32_t*)&t;
}

// ---------------- CSR build ----------------
__global__ __launch_bounds__(256) void hist_kernel(
    const int* __restrict__ dst, int E, int* __restrict__ deg)
{
    int i = blockIdx.x * 256 + threadIdx.x;
    if (i < E) atomicAdd(&deg[dst[i]], 1);
}

__global__ __launch_bounds__(1024) void scan_kernel(
    const int* __restrict__ deg, int n, int* __restrict__ ptr, int* __restrict__ cur)
{
    __shared__ int ssum[1024];
    const int tid = threadIdx.x;
    const int chunk = (n + 1023) >> 10;
    const int start = tid * chunk;
    int s = 0;
    for (int i = 0; i < chunk; i++) {
        int idx = start + i;
        if (idx < n) s += deg[idx];
    }
    ssum[tid] = s;
    __syncthreads();
    for (int off = 1; off < 1024; off <<= 1) {
        int v = 0;
        if (tid >= off) v = ssum[tid - off];
        __syncthreads();
        ssum[tid] += v;
        __syncthreads();
    }
    int base = ssum[tid] - s;   // exclusive
    for (int i = 0; i < chunk; i++) {
        int idx = start + i;
        if (idx < n) {
            ptr[idx] = base;
            cur[idx] = base;
            base += deg[idx];
        }
    }
    if (tid == 1023) ptr[n] = ssum[1023];
}

__global__ __launch_bounds__(256) void scatter_kernel(
    const int* __restrict__ src, const int* __restrict__ dst, int E,
    int* __restrict__ cur, int* __restrict__ esrc, int* __restrict__ eidx)
{
    int i = blockIdx.x * 256 + threadIdx.x;
    if (i < E) {
        int p = atomicAdd(&cur[dst[i]], 1);
        esrc[p] = src[i];
        eidx[p] = i;
    }
}

// gather edge_attr into dst-sorted order (once per launch; reused by 3 layers)
__global__ __launch_bounds__(256) void gather_ea(
    const float* __restrict__ ea, const int* __restrict__ eidx,
    float* __restrict__ ea_s, int E)
{
    int i = blockIdx.x * 256 + threadIdx.x;   // one float4 slot per thread
    if (i < E * 4) {
        int p = i >> 2, c = i & 3;
        int e = __ldg(&eidx[p]);
        *(float4*)(ea_s + (size_t)p * 16 + c * 4) =
            *(const float4*)(ea + (size_t)e * 16 + c * 4);
    }
}

// ---------------- W split: W[k][n] fp32 -> Whi/Wlo[n][k] bf16 ----------------
__global__ __launch_bounds__(256) void conv_w(
    const float* __restrict__ W,
    __nv_bfloat16* __restrict__ Whi, __nv_bfloat16* __restrict__ Wlo)
{
    for (int i = blockIdx.x * 256 + threadIdx.x; i < 128 * 128; i += gridDim.x * 256) {
        int k = i >> 7, n = i & 127;
        float v = W[i];
        __nv_bfloat16 h = __float2bfloat16(v);
        float lo = v - __bfloat162float(h);
        Whi[n * 128 + k] = h;
        Wlo[n * 128 + k] = __float2bfloat16(lo);
    }
}

// =================================================================
// HMMA GEMM: C[M x 128] = f(A[M x 128]) @ W[128 x 128] + bias
//   f = identity if gstats==nullptr, else relu(bn(A))
// fp32 emulated as bf16 split: Ahi*Bhi + Alo*Bhi + Ahi*Blo
// =================================================================
__global__ __launch_bounds__(256, 2) void mma_gemm(
    const float* __restrict__ A,
    const __nv_bfloat16* __restrict__ Whi, const __nv_bfloat16* __restrict__ Wlo,
    const float* __restrict__ bias,
    const float* __restrict__ gstats, const float* __restrict__ gamma,
    const float* __restrict__ beta, float invM,
    float* __restrict__ C, int M)
{
    __shared__ __align__(16) __nv_bfloat16 sAhi[128 * 40];
    __shared__ __align__(16) __nv_bfloat16 sAlo[128 * 40];
    __shared__ __align__(16) __nv_bfloat16 sBhi[128 * 40];
    __shared__ __align__(16) __nv_bfloat16 sBlo[128 * 40];
    __shared__ float sBias[128];
    __shared__ float sSc[128];
    __shared__ float sSh[128];

    const int tid = threadIdx.x;
    const int wid = tid >> 5, lane = tid & 31;
    const int wm = wid & 3, wn = wid >> 2;      // 4 (M) x 2 (N) warps
    const int m0 = blockIdx.x * 128;
    const bool dobn = (gstats != nullptr);

    if (tid < 128) {
        sBias[tid] = bias[tid];
        if (dobn) {
            float m = gstats[tid] * invM;
            float v = gstats[128 + tid] * invM - m * m;
            float sc = gamma[tid] * rsqrtf(v + 1e-5f);
            sSc[tid] = sc;
            sSh[tid] = beta[tid] - m * sc;
        }
    }
    __syncthreads();

    float acc[2][8][4];
    #pragma unroll
    for (int i = 0; i < 2; i++)
        #pragma unroll
        for (int j = 0; j < 8; j++)
            #pragma unroll
            for (int q = 0; q < 4; q++) acc[i][j][q] = 0.f;

    const uint32_t aHiB = smem_to_u32(sAhi), aLoB = smem_to_u32(sAlo);
    const uint32_t bHiB = smem_to_u32(sBhi), bLoB = smem_to_u32(sBlo);

    const uint32_t aoffL = (uint32_t)(((wm * 32 + (lane & 15)) * 40 + ((lane >> 4) << 3)) * 2);
    const uint32_t boffL = (uint32_t)(((wn * 64 + ((lane >> 4) << 3) + (lane & 7)) * 40
                                      + (((lane >> 3) & 1) << 3)) * 2);

    for (int kc = 0; kc < 128; kc += 32) {
        if (kc) __syncthreads();

        // ---- A chunk: 128 rows x 32 cols fp32 -> bf16 hi/lo ----
        #pragma unroll
        for (int i = 0; i < 4; i++) {
            int linear = tid + i * 256;
            int r = linear >> 3;
            int c4 = (linear & 7) * 4;
            int gr = m0 + r;
            float4 v = make_float4(0.f, 0.f, 0.f, 0.f);
            if (gr < M) {
                v = *(const float4*)(A + (size_t)gr * 128 + kc + c4);
                if (dobn) {
                    int kcc = kc + c4;
                    float4 sc = *(const float4*)&sSc[kcc];
                    float4 sh = *(const float4*)&sSh[kcc];
                    v.x = fmaxf(fmaf(v.x, sc.x, sh.x), 0.f);
                    v.y = fmaxf(fmaf(v.y, sc.y, sh.y), 0.f);
                    v.z = fmaxf(fmaf(v.z, sc.z, sh.z), 0.f);
                    v.w = fmaxf(fmaf(v.w, sc.w, sh.w), 0.f);
                }
            }
            __nv_bfloat16 hx = __float2bfloat16(v.x), hy = __float2bfloat16(v.y);
            __nv_bfloat16 hz = __float2bfloat16(v.z), hw = __float2bfloat16(v.w);
            float lx = v.x - __bfloat162float(hx), ly = v.y - __bfloat162float(hy);
            float lz = v.z - __bfloat162float(hz), lw = v.w - __bfloat162float(hw);
            int base = r * 40 + c4;
            __nv_bfloat162 h0; h0.x = hx; h0.y = hy;
            __nv_bfloat162 h1; h1.x = hz; h1.y = hw;
            *(uint32_t*)&sAhi[base]     = *(uint32_t*)&h0;
            *(uint32_t*)&sAhi[base + 2] = *(uint32_t*)&h1;
            *(uint32_t*)&sAlo[base]     = pack2(lx, ly);
            *(uint32_t*)&sAlo[base + 2] = pack2(lz, lw);
        }

        // ---- B chunk: copy pre-split [n][k] bf16 ----
        #pragma unroll
        for (int i = 0; i < 2; i++) {
            int linear = tid + i * 256;
            int r = linear >> 2;
            int c8 = (linear & 3) * 8;
            *(uint4*)&sBhi[r * 40 + c8] = *(const uint4*)(Whi + (size_t)r * 128 + kc + c8);
            *(uint4*)&sBlo[r * 40 + c8] = *(const uint4*)(Wlo + (size_t)r * 128 + kc + c8);
        }
        __syncthreads();

        #pragma unroll
        for (int ks = 0; ks < 2; ks++) {
            const uint32_t ko = (uint32_t)(ks * 16 * 2);
            uint32_t ahi[8], alo[8], bf[16];
            ldsm4(ahi,     aHiB + aoffL + ko);
            ldsm4(ahi + 4, aHiB + aoffL + ko + 16 * 40 * 2);
            ldsm4(alo,     aLoB + aoffL + ko);
            ldsm4(alo + 4, aLoB + aoffL + ko + 16 * 40 * 2);
            ldsm4(bf,      bHiB + boffL + ko);
            ldsm4(bf + 4,  bHiB + boffL + ko + 16 * 40 * 2);
            ldsm4(bf + 8,  bHiB + boffL + ko + 32 * 40 * 2);
            ldsm4(bf + 12, bHiB + boffL + ko + 48 * 40 * 2);
            #pragma unroll
            for (int mt = 0; mt < 2; mt++)
                #pragma unroll
                for (int nt = 0; nt < 8; nt++) {
                    mma16816(acc[mt][nt], ahi + mt * 4, bf + nt * 2);
                    mma16816(acc[mt][nt], alo + mt * 4, bf + nt * 2);
                }
            ldsm4(bf,      bLoB + boffL + ko);
            ldsm4(bf + 4,  bLoB + boffL + ko + 16 * 40 * 2);
            ldsm4(bf + 8,  bLoB + boffL + ko + 32 * 40 * 2);
            ldsm4(bf + 12, bLoB + boffL + ko + 48 * 40 * 2);
            #pragma unroll
            for (int mt = 0; mt < 2; mt++)
                #pragma unroll
                for (int nt = 0; nt < 8; nt++)
                    mma16816(acc[mt][nt], ahi + mt * 4, bf + nt * 2);
        }
    }

    #pragma unroll
    for (int mt = 0; mt < 2; mt++) {
        int r0 = m0 + wm * 32 + mt * 16 + (lane >> 2);
        #pragma unroll
        for (int nt = 0; nt < 8; nt++) {
            int c = wn * 64 + nt * 8 + (lane & 3) * 2;
            float b0 = sBias[c], b1 = sBias[c + 1];
            if (r0 < M) {
                float2 o = make_float2(acc[mt][nt][0] + b0, acc[mt][nt][1] + b1);
                *(float2*)(C + (size_t)r0 * 128 + c) = o;
            }
            if (r0 + 8 < M) {
                float2 o = make_float2(acc[mt][nt][2] + b0, acc[mt][nt][3] + b1);
                *(float2*)(C + (size_t)(r0 + 8) * 128 + c) = o;
            }
        }
    }
}

// =================================================================
// scalar GEMM (projection only, K=64): C = A@W + bias
// =================================================================
__global__ __launch_bounds__(256) void gemm_kernel(
    const float* __restrict__ A, const float* __restrict__ W,
    const float* __restrict__ bias,
    float* __restrict__ C, int M, int K)
{
    constexpr int BM = 128, BN = 128, BK = 16;
    __shared__ __align__(16) float As[BK][BM + 4];
    __shared__ __align__(16) float Bs[BK][BN];

    const int tid = threadIdx.x;
    const int m0 = blockIdx.x * BM;
    const int tx = tid & 15;
    const int ty = tid >> 4;

    float acc[8][8];
    #pragma unroll
    for (int i = 0; i < 8; i++)
        #pragma unroll
        for (int j = 0; j < 8; j++) acc[i][j] = 0.f;

    for (int kb = 0; kb < K; kb += BK) {
        #pragma unroll
        for (int i = 0; i < 2; i++) {
            int idx = tid + i * 256;
            int r = idx >> 2, c4 = idx & 3;
            int gr = m0 + r;
            float4 v = make_float4(0.f, 0.f, 0.f, 0.f);
            if (gr < M) v = *(const float4*)(A + (size_t)gr * K + kb + c4 * 4);
            As[c4 * 4 + 0][r] = v.x;
            As[c4 * 4 + 1][r] = v.y;
            As[c4 * 4 + 2][r] = v.z;
            As[c4 * 4 + 3][r] = v.w;
        }
        #pragma unroll
        for (int i = 0; i < 2; i++) {
            int idx = tid + i * 256;
            int r = idx >> 5, c4 = idx & 31;
            *(float4*)&Bs[r][c4 * 4] =
                *(const float4*)(W + (size_t)(kb + r) * BN + c4 * 4);
        }
        __syncthreads();

        #pragma unroll
        for (int kk = 0; kk < BK; kk++) {
            float4 a0 = *(const float4*)&As[kk][ty * 8];
            float4 a1 = *(const float4*)&As[kk][ty * 8 + 4];
            float4 b0 = *(const float4*)&Bs[kk][tx * 8];
            float4 b1 = *(const float4*)&Bs[kk][tx * 8 + 4];
            float av[8] = {a0.x, a0.y, a0.z, a0.w, a1.x, a1.y, a1.z, a1.w};
            float bv[8] = {b0.x, b0.y, b0.z, b0.w, b1.x, b1.y, b1.z, b1.w};
            #pragma unroll
            for (int i = 0; i < 8; i++)
                #pragma unroll
                for (int j = 0; j < 8; j++)
                    acc[i][j] = fmaf(av[i], bv[j], acc[i][j]);
        }
        __syncthreads();
    }

    float4 bv0 = *(const float4*)(bias + tx * 8);
    float4 bv1 = *(const float4*)(bias + tx * 8 + 4);
    float bb[8] = {bv0.x, bv0.y, bv0.z, bv0.w, bv1.x, bv1.y, bv1.z, bv1.w};

    #pragma unroll
    for (int i = 0; i < 8; i++) {
        int gr = m0 + ty * 8 + i;
        if (gr < M) {
            float4 o0 = make_float4(acc[i][0] + bb[0], acc[i][1] + bb[1],
                                    acc[i][2] + bb[2], acc[i][3] + bb[3]);
            float4 o1 = make_float4(acc[i][4] + bb[4], acc[i][5] + bb[5],
                                    acc[i][6] + bb[6], acc[i][7] + bb[7]);
            *(float4*)(C + (size_t)gr * BN + tx * 8)     = o0;
            *(float4*)(C + (size_t)gr * BN + tx * 8 + 4) = o1;
        }
    }
}

// ---------------- fast column stats: out[0..127]=sum, out[128..255]=sumsq ----------------
__global__ __launch_bounds__(256) void stats_fast(
    const float* __restrict__ T, int M, float* __restrict__ out)
{
    __shared__ float sS[8 * 128];
    __shared__ float sQ[8 * 128];
    const int tid = threadIdx.x, w = tid >> 5, l = tid & 31;
    const int c4 = l * 4;
    float4 s = make_float4(0.f, 0.f, 0.f, 0.f);
    float4 q = make_float4(0.f, 0.f, 0.f, 0.f);
    for (int r = blockIdx.x * 8 + w; r < M; r += gridDim.x * 8) {
        float4 v = *(const float4*)(T + (size_t)r * 128 + c4);
        s.x += v.x; q.x = fmaf(v.x, v.x, q.x);
        s.y += v.y; q.y = fmaf(v.y, v.y, q.y);
        s.z += v.z; q.z = fmaf(v.z, v.z, q.z);
        s.w += v.w; q.w = fmaf(v.w, v.w, q.w);
    }
    *(float4*)&sS[w * 128 + c4] = s;
    *(float4*)&sQ[w * 128 + c4] = q;
    __syncthreads();
    if (tid < 128) {
        float a = 0.f, b = 0.f;
        #pragma unroll
        for (int ww = 0; ww < 8; ww++) {
            a += sS[ww * 128 + tid];
            b += sQ[ww * 128 + tid];
        }
        atomicAdd(&out[tid], a);
        atomicAdd(&out[128 + tid], b);
    }
}

// =================================================================
// node-centric aggregation v2 (atomic-free):
//   agg[n] = h[n] + sum_{e in csr[n]} relu(h[esrc[e]] + ea_s[e] @ We + be)
// warp per node; We held in registers (lane owns 4 output cols x 16 k);
// 2 edges per iteration (lanes 0-15 carry edge e attrs, 16-31 edge e+1).
// =================================================================
__global__ __launch_bounds__(256, 2) void node_agg2(
    const float* __restrict__ h, const float* __restrict__ ea_s,
    const int* __restrict__ ptr, const int* __restrict__ esrc,
    const float* __restrict__ We, const float* __restrict__ be,
    float* __restrict__ agg, int Nn)
{
    const int tid = threadIdx.x;
    const int warp = tid >> 5, lid = tid & 31;
    const int j0 = lid * 4;

    float4 wr[16];
    #pragma unroll
    for (int k = 0; k < 16; k++) wr[k] = *(const float4*)(We + k * 128 + j0);
    const float4 bv = *(const float4*)(be + j0);

    for (int n = blockIdx.x * 8 + warp; n < Nn; n += gridDim.x * 8) {
        const int lo = ptr[n], hi = ptr[n + 1];
        float4 acc = *(const float4*)(h + (size_t)n * 128 + j0);
        int e = lo;
        for (; e + 1 < hi; e += 2) {
            // one coalesced 128B load: 32 floats = attrs of edges e and e+1
            float v = ea_s[(size_t)e * 16 + lid];
            int s0 = __ldg(&esrc[e]);
            int s1 = __ldg(&esrc[e + 1]);
            float4 h0 = *(const float4*)(h + (size_t)s0 * 128 + j0);
            float4 h1 = *(const float4*)(h + (size_t)s1 * 128 + j0);
            float4 m0 = bv, m1 = bv;
            #pragma unroll
            for (int k = 0; k < 16; k++) {
                float a0 = __shfl_sync(0xffffffffu, v, k);
                float a1 = __shfl_sync(0xffffffffu, v, k + 16);
                m0.x = fmaf(a0, wr[k].x, m0.x);  m1.x = fmaf(a1, wr[k].x, m1.x);
                m0.y = fmaf(a0, wr[k].y, m0.y);  m1.y = fmaf(a1, wr[k].y, m1.y);
                m0.z = fmaf(a0, wr[k].z, m0.z);  m1.z = fmaf(a1, wr[k].z, m1.z);
                m0.w = fmaf(a0, wr[k].w, m0.w);  m1.w = fmaf(a1, wr[k].w, m1.w);
            }
            acc.x += fmaxf(m0.x + h0.x, 0.f) + fmaxf(m1.x + h1.x, 0.f);
            acc.y += fmaxf(m0.y + h0.y, 0.f) + fmaxf(m1.y + h1.y, 0.f);
            acc.z += fmaxf(m0.z + h0.z, 0.f) + fmaxf(m1.z + h1.z, 0.f);
            acc.w += fmaxf(m0.w + h0.w, 0.f) + fmaxf(m1.w + h1.w, 0.f);
        }
        if (e < hi) {
            float v = (lid < 16) ? ea_s[(size_t)e * 16 + lid] : 0.f;
            int s0 = __ldg(&esrc[e]);
            float4 h0 = *(const float4*)(h + (size_t)s0 * 128 + j0);
            float4 m0 = bv;
            #pragma unroll
            for (int k = 0; k < 16; k++) {
                float a0 = __shfl_sync(0xffffffffu, v, k);
                m0.x = fmaf(a0, wr[k].x, m0.x);
                m0.y = fmaf(a0, wr[k].y, m0.y);
                m0.z = fmaf(a0, wr[k].z, m0.z);
                m0.w = fmaf(a0, wr[k].w, m0.w);
            }
            acc.x += fmaxf(m0.x + h0.x, 0.f);
            acc.y += fmaxf(m0.y + h0.y, 0.f);
            acc.z += fmaxf(m0.z + h0.z, 0.f);
            acc.w += fmaxf(m0.w + h0.w, 0.f);
        }
        *(float4*)(agg + (size_t)n * 128 + j0) = acc;
    }
}

// ---------------- bn+relu apply ----------------
__global__ __launch_bounds__(256) void bn_apply_kernel(
    const float* __restrict__ T, const float* __restrict__ gstats,
    const float* __restrict__ gamma, const float* __restrict__ beta, float invM,
    float* __restrict__ outl, int total4)
{
    __shared__ float sSc[128];
    __shared__ float sSh[128];
    if (threadIdx.x < 128) {
        int c = threadIdx.x;
        float m = gstats[c] * invM;
        float v = gstats[128 + c] * invM - m * m;
        float sc = gamma[c] * rsqrtf(v + 1e-5f);
        sSc[c] = sc;
        sSh[c] = beta[c] - m * sc;
    }
    __syncthreads();
    int i = blockIdx.x * blockDim.x + threadIdx.x;
    if (i < total4) {
        int c4 = (i & 31) * 4;
        float4 v = *(const float4*)(T + (size_t)i * 4);
        float4 sc = *(const float4*)&sSc[c4];
        float4 sh = *(const float4*)&sSh[c4];
        float4 r;
        r.x = fmaxf(fmaf(v.x, sc.x, sh.x), 0.f);
        r.y = fmaxf(fmaf(v.y, sc.y, sh.y), 0.f);
        r.z = fmaxf(fmaf(v.z, sc.z, sh.z), 0.f);
        r.w = fmaxf(fmaf(v.w, sc.w, sh.w), 0.f);
        *(float4*)(outl + (size_t)i * 4) = r;
    }
}

// ---------------- pooling ----------------
__device__ __forceinline__ int lower_bound_i(const int* a, int n, int key) {
    int lo = 0, hi = n;
    while (lo < hi) { int mid = (lo + hi) >> 1; if (a[mid] < key) lo = mid + 1; else hi = mid; }
    return lo;
}

__global__ __launch_bounds__(384) void pool_kernel(
    const float* __restrict__ o0, const float* __restrict__ o1, const float* __restrict__ o2,
    const int* __restrict__ batch, int Nn, float* __restrict__ zcat)
{
    const int g = blockIdx.x;
    const int lo = lower_bound_i(batch, Nn, g);
    const int hi = lower_bound_i(batch, Nn, g + 1);
    const int c = threadIdx.x;
    const float* src = (c < 128) ? o0 : ((c < 256) ? o1 : o2);
    const int cc = c & 127;
    float s = 0.f, mx = 0.f;
    for (int n = lo; n < hi; n++) {
        float v = src[(size_t)n * 128 + cc];
        s += v; mx = fmaxf(mx, v);
    }
    int cnt = hi - lo;
    float mean = s / (float)(cnt > 0 ? cnt : 1);
    zcat[(size_t)g * 768 + c]       = mean;
    zcat[(size_t)g * 768 + 384 + c] = mx;
}

// ---------------- head ----------------
__global__ __launch_bounds__(128) void head1_kernel(
    const float* __restrict__ zcat, const float* __restrict__ W1,
    const float* __restrict__ b1, float* __restrict__ zh)
{
    __shared__ __align__(16) float zs[768];
    const int g = blockIdx.x;
    for (int k = threadIdx.x; k < 768; k += 128) zs[k] = zcat[(size_t)g * 768 + k];
    __syncthreads();
    const int j = threadIdx.x;
    float acc = b1[j];
    #pragma unroll 8
    for (int k = 0; k < 768; k++) acc = fmaf(zs[k], W1[(size_t)k * 128 + j], acc);
    zh[(size_t)g * 128 + j] = acc;
}

__global__ __launch_bounds__(128) void head_stats_kernel(
    const float* __restrict__ zh, const float* __restrict__ g, const float* __restrict__ b,
    int G, float* __restrict__ sc_sh)
{
    int c = threadIdx.x;
    float s = 0.f, s2 = 0.f;
    for (int r = 0; r < G; r++) { float v = zh[(size_t)r * 128 + c]; s += v; s2 = fmaf(v, v, s2); }
    float invG = 1.f / (float)G;
    float m = s * invG;
    float var = s2 * invG - m * m;
    float sc = g[c] * rsqrtf(var + 1e-5f);
    sc_sh[c] = sc;
    sc_sh[128 + c] = b[c] - m * sc;
}

__global__ __launch_bounds__(128) void head2_kernel(
    const float* __restrict__ zh, const float* __restrict__ sc_sh,
    const float* __restrict__ W2, const float* __restrict__ b2, float* __restrict__ out)
{
    __shared__ float red[128];
    const int g = blockIdx.x, j = threadIdx.x;
    float v = fmaxf(fmaf(zh[(size_t)g * 128 + j], sc_sh[j], sc_sh[128 + j]), 0.f) * W2[j];
    red[j] = v;
    __syncthreads();
    #pragma unroll
    for (int s = 64; s > 0; s >>= 1) {
        if (j < s) red[j] += red[j + s];
        __syncthreads();
    }
    if (j == 0) out[g] = red[0] + b2[0];
}

// ---------------- launcher ----------------
extern "C" void kernel_launch(void* const* d_in, const int* in_sizes, int n_in,
                              void* d_out, int out_size)
{
    const float* x         = (const float*)d_in[0];
    const float* edge_attr = (const float*)d_in[1];
    const int*   src       = (const int*)  d_in[2];
    const int*   dst       = (const int*)  d_in[3];
    const int*   batch     = (const int*)  d_in[4];
    const float* Wp        = (const float*)d_in[5];
    const float* bp        = (const float*)d_in[6];
    const float* conv_We   = (const float*)d_in[7];
    const float* conv_be   = (const float*)d_in[8];
    const float* conv_W1   = (const float*)d_in[9];
    const float* conv_b1   = (const float*)d_in[10];
    const float* conv_g1   = (const float*)d_in[11];
    const float* conv_bt1  = (const float*)d_in[12];
    const float* conv_W2   = (const float*)d_in[13];
    const float* conv_b2   = (const float*)d_in[14];
    const float* bn_g      = (const float*)d_in[15];
    const float* bn_b      = (const float*)d_in[16];
    const float* head_W1   = (const float*)d_in[17];
    const float* head_b1   = (const float*)d_in[18];
    const float* head_g    = (const float*)d_in[19];
    const float* head_bt   = (const float*)d_in[20];
    const float* head_W2   = (const float*)d_in[21];
    const float* head_b2   = (const float*)d_in[22];

    const int Nn = in_sizes[0] / 64;     // 50000
    const int E  = in_sizes[2];          // 800000
    const int G  = out_size;             // 256

    float *hp, *agg, *t, *outl, *zcat, *zh, *stats, *hsc, *eas;
    __nv_bfloat16 *whi, *wlo;
    int *deg, *ptr, *cur, *esrc, *eidx;
    cudaGetSymbolAddress((void**)&hp,    d_hp);
    cudaGetSymbolAddress((void**)&agg,   d_agg);
    cudaGetSymbolAddress((void**)&t,     d_t);
    cudaGetSymbolAddress((void**)&outl,  d_outl);
    cudaGetSymbolAddress((void**)&zcat,  d_zcat);
    cudaGetSymbolAddress((void**)&zh,    d_zh);
    cudaGetSymbolAddress((void**)&stats, d_stats);
    cudaGetSymbolAddress((void**)&hsc,   d_hsc);
    cudaGetSymbolAddress((void**)&whi,   d_whi);
    cudaGetSymbolAddress((void**)&wlo,   d_wlo);
    cudaGetSymbolAddress((void**)&deg,   d_deg);
    cudaGetSymbolAddress((void**)&ptr,   d_ptr);
    cudaGetSymbolAddress((void**)&cur,   d_cur);
    cudaGetSymbolAddress((void**)&esrc,  d_esrc);
    cudaGetSymbolAddress((void**)&eidx,  d_eidx);
    cudaGetSymbolAddress((void**)&eas,   d_eas);

    const int gB = (Nn + 127) / 128;
    const int gE = (E + 255) / 256;
    const float invM = 1.f / (float)Nn;
    const int total4 = Nn * 32;          // N*128/4

    // zero BN stat accumulators + degree histogram (re-done every launch -> replay-safe)
    cudaMemsetAsync(stats, 0, 6 * 256 * sizeof(float), 0);
    cudaMemsetAsync(deg, 0, (size_t)Nn * sizeof(int), 0);

    // CSR by dst + ea pre-gather (dst/edge_attr layer-invariant; build once, use 3x)
    hist_kernel<<<gE, 256>>>(dst, E, deg);
    scan_kernel<<<1, 1024>>>(deg, Nn, ptr, cur);
    scatter_kernel<<<gE, 256>>>(src, dst, E, cur, esrc, eidx);
    gather_ea<<<(E * 4 + 255) / 256, 256>>>(edge_attr, eidx, eas, E);

    // projection: h = x @ Wp + bp
    gemm_kernel<<<gB, 256>>>(x, Wp, bp, hp, Nn, 64);

    const float* h = hp;
    for (int l = 0; l < 3; l++) {
        const float* We_l = conv_We + (size_t)l * 16 * 128;
        const float* be_l = conv_be + (size_t)l * 128;
        const float* W1_l = conv_W1 + (size_t)l * 128 * 128;
        const float* b1_l = conv_b1 + (size_t)l * 128;
        const float* g1_l = conv_g1 + (size_t)l * 128;
        const float* t1_l = conv_bt1 + (size_t)l * 128;
        const float* W2_l = conv_W2 + (size_t)l * 128 * 128;
        const float* b2_l = conv_b2 + (size_t)l * 128;
        const float* bg_l = bn_g + (size_t)l * 128;
        const float* bb_l = bn_b + (size_t)l * 128;
        float* outl_l = outl + (size_t)l * Nn * 128;
        float* S0 = stats + (size_t)(2 * l) * 256;
        float* S1 = stats + (size_t)(2 * l + 1) * 256;

        // agg[n] = h[n] + sum incoming relu(h[src] + ea@We + be)   (atomic-free)
        node_agg2<<<2048, 256>>>(h, eas, ptr, esrc, We_l, be_l, agg, Nn);

        // t1 = agg @ W1 + b1 (HMMA bf16-split)
        conv_w<<<64, 256>>>(W1_l, whi, wlo);
        mma_gemm<<<gB, 256>>>(agg, whi, wlo, b1_l,
                              nullptr, nullptr, nullptr, 0.f, t, Nn);
        stats_fast<<<512, 256>>>(t, Nn, S0);

        // t2 = relu(bn_{S0}(t1)) @ W2 + b2 (in place, HMMA)
        conv_w<<<64, 256>>>(W2_l, whi, wlo);
        mma_gemm<<<gB, 256>>>(t, whi, wlo, b2_l,
                              S0, g1_l, t1_l, invM, t, Nn);
        stats_fast<<<512, 256>>>(t, Nn, S1);

        // out_l = relu(bn_{S1}(t2))
        bn_apply_kernel<<<(total4 + 255) / 256, 256>>>(
            t, S1, bg_l, bb_l, invM, outl_l, total4);

        h = outl_l;
    }

    pool_kernel<<<G, 384>>>(outl, outl + (size_t)Nn * 128, outl + (size_t)2 * Nn * 128,
                            batch, Nn, zcat);
    head1_kernel<<<G, 128>>>(zcat, head_W1, head_b1, zh);
    head_stats_kernel<<<1, 128>>>(zh, head_g, head_bt, G, hsc);
    head2_kernel<<<G, 128>>>(zh, hsc, head_W2, head_b2, (float*)d_out);
}